// round 17
// baseline (speedup 1.0000x reference)
#include <cuda_runtime.h>
#include <cuda_fp16.h>
#include <cstdint>

// ---------------- problem dimensions ----------------
#define PN1 100000
#define PE1 1600000
#define PD  128
#define PN2 1024
#define PE2 200000
#define PNB 30
#define ZS_ACC 8
#define KT_ACC 248            // (31744/16) / 8

// GEMM smem rows: 16 halves padded to 48 B
#define ROW_B 48
#define STAGE_B (128 * ROW_B)

// linear1 smem rows: 64 halves padded to 144 B
#define LROW_H 72

// fused_main role split
#define NG1 1920              // gemm1 tiles (8 x 8 x 30)
#define NSC 6144              // scatter blocks
#define SC_STRIDE (NSC * 8)   // warps doing scatter

// fused_prep role boundaries
#define RB_ZA   8192                      // zero_A
#define RB_ZM   (RB_ZA + 4096)            // zero_main
#define RB_DEG  (RB_ZM + 782)             // deg2
#define RB_TB   (RB_DEG + 30720)          // transpose_basis
#define RB_TX   (RB_TB + 1024)            // transpose_x
#define RB_TR   (RB_TX + 1024)            // transpose_root
#define RB_CX   (RB_TR + 512)             // convert_X
#define RB_TW   (RB_CX + 16)              // transpose_W
#define PREP_GRID RB_TW                   // 46366

// ---------------- device scratch ----------------
__device__ __align__(16) float  g_deg1[PN1];
__device__ __align__(16) float  g_agg1[(size_t)PN1 * PD];
__device__ __align__(16) float  g_deg2[PN2];
__device__ __align__(16) float  g_A[(size_t)PNB * PN2 * PN2];
__device__ __align__(16) __half g_Ah[(size_t)PNB * PN2 * PN2];
__device__ __align__(16) __half g_Sh[(size_t)PNB * PN2 * PN2];
__device__ __align__(16) __half g_Xth[(size_t)PN2 * PN2];
__device__ __align__(16) __half g_Xh[(size_t)PN2 * PN2];
__device__ __align__(16) __half g_Bth[(size_t)(PNB + 1) * PN2 * PN2];
__device__ __align__(16) __half g_Wth[PD * PD];
__device__ __align__(16) float  g_h2[(size_t)PN2 * PN2];
__device__ int g_is64;

// ---------------- helpers ----------------
__device__ __forceinline__ int load_idx(const void* p, size_t idx) {
    if (g_is64) return (int)((const long long*)p)[idx];
    return ((const int*)p)[idx];
}

__device__ __forceinline__ uint32_t smem_u32(const void* p) {
    uint32_t r;
    asm("{ .reg .u64 t; cvta.to.shared.u64 t, %1; cvt.u32.u64 %0, t; }"
        : "=r"(r) : "l"(p));
    return r;
}

__device__ __forceinline__ void ldsm4(uint32_t& r0, uint32_t& r1, uint32_t& r2,
                                      uint32_t& r3, uint32_t addr) {
    asm volatile("ldmatrix.sync.aligned.m8n8.x4.shared.b16 {%0,%1,%2,%3}, [%4];"
                 : "=r"(r0), "=r"(r1), "=r"(r2), "=r"(r3) : "r"(addr));
}

__device__ __forceinline__ void mma_f16(float* c, uint32_t a0, uint32_t a1,
                                        uint32_t a2, uint32_t a3,
                                        uint32_t b0, uint32_t b1) {
    asm volatile(
        "mma.sync.aligned.m16n8k16.row.col.f32.f16.f16.f32 "
        "{%0,%1,%2,%3},{%4,%5,%6,%7},{%8,%9},{%0,%1,%2,%3};"
        : "+f"(c[0]), "+f"(c[1]), "+f"(c[2]), "+f"(c[3])
        : "r"(a0), "r"(a1), "r"(a2), "r"(a3), "r"(b0), "r"(b1));
}

__device__ __forceinline__ void cp16(uint32_t s, const void* g) {
    asm volatile("cp.async.cg.shared.global [%0], [%1], 16;" :: "r"(s), "l"(g));
}
#define CP_COMMIT() asm volatile("cp.async.commit_group;")
#define CP_WAIT2()  asm volatile("cp.async.wait_group 2;")

__device__ __forceinline__ void compute_k16(uint32_t AsU, uint32_t BsU,
                                            int base_a, int base_b,
                                            float (&acc)[2][8][4]) {
    uint32_t a[2][4];
    ldsm4(a[0][0], a[0][1], a[0][2], a[0][3], AsU + base_a);
    ldsm4(a[1][0], a[1][1], a[1][2], a[1][3], AsU + base_a + 16 * ROW_B);
#pragma unroll
    for (int j = 0; j < 4; j++) {
        uint32_t b0, b1, b2, b3;
        ldsm4(b0, b1, b2, b3, BsU + base_b + j * (16 * ROW_B));
        mma_f16(acc[0][2 * j],     a[0][0], a[0][1], a[0][2], a[0][3], b0, b2);
        mma_f16(acc[0][2 * j + 1], a[0][0], a[0][1], a[0][2], a[0][3], b1, b3);
        mma_f16(acc[1][2 * j],     a[1][0], a[1][1], a[1][2], a[1][3], b0, b2);
        mma_f16(acc[1][2 * j + 1], a[1][0], a[1][1], a[1][2], a[1][3], b1, b3);
    }
}

// =====================================================================
// probe (+ zero g_deg2, so prep can atomically count into it)
// =====================================================================
__global__ void probe_kernel(const int* __restrict__ ei_words) {
    __shared__ int found;
    if (threadIdx.x == 0) found = 0;
    __syncthreads();
    for (int i = threadIdx.x; i < 4096; i += 256)
        if (ei_words[2 * i + 1] != 0) found = 1;
    __syncthreads();
    if (threadIdx.x == 0) g_is64 = found ? 0 : 1;
    for (int i = threadIdx.x; i < PN2; i += 256) g_deg2[i] = 0.0f;
}

// =====================================================================
// fused_prep: zero_A | zero_main | deg2 | transposes | convert_X | W^T
// =====================================================================
__device__ __forceinline__ void transpose_body(__half* dst,
                                               const float* __restrict__ src,
                                               int bx, int by, int tx, int ty,
                                               float (*tile)[33]) {
    int c = bx * 32 + tx, r = by * 32 + ty;
#pragma unroll
    for (int i = 0; i < 32; i += 8)
        tile[ty + i][tx] = src[(size_t)(r + i) * PN2 + c];
    __syncthreads();
    c = by * 32 + tx; r = bx * 32 + ty;
#pragma unroll
    for (int i = 0; i < 32; i += 8)
        dst[(size_t)(r + i) * PN2 + c] = __float2half_rn(tile[tx][ty + i]);
}

__global__ void fused_prep(const float* __restrict__ x_g2,
                           const float* __restrict__ basis,
                           const float* __restrict__ root,
                           const float* __restrict__ W_stc,
                           const void* __restrict__ ei2) {
    __shared__ float tile[32][33];
    const int bid = blockIdx.x, tid = threadIdx.x;
    const int tx = tid & 31, ty = tid >> 5;
    const float4 z4 = make_float4(0.f, 0.f, 0.f, 0.f);

    if (bid < RB_ZA) {                       // zero g_A (fp32)
        for (size_t i = (size_t)bid * 256 + tid; i < ((size_t)PNB << 20) / 4;
             i += (size_t)RB_ZA * 256)
            ((float4*)g_A)[i] = z4;
    } else if (bid < RB_ZM) {                // zero agg1/deg1/h2
        const size_t b = (size_t)(bid - RB_ZA) * 256 + tid;
        const size_t st = (size_t)4096 * 256;
        for (size_t i = b; i < (size_t)PN1 * PD / 4; i += st) ((float4*)g_agg1)[i] = z4;
        if (b < PN1 / 4)               ((float4*)g_deg1)[b] = z4;
        if (b < (size_t)PN2 * PN2 / 4) ((float4*)g_h2)[b] = z4;
    } else if (bid < RB_DEG) {               // deg2 count
        const int e = (bid - RB_ZM) * 256 + tid;
        if (e < PE2) atomicAdd(&g_deg2[load_idx(ei2, (size_t)PE2 + e)], 1.0f);
    } else if (bid < RB_TB) {                // transpose basis -> Bth
        const int t = bid - RB_DEG;
        const int z = t >> 10, rem = t & 1023;
        transpose_body(g_Bth + ((size_t)z << 20), basis + ((size_t)z << 20),
                       rem & 31, rem >> 5, tx, ty, tile);
    } else if (bid < RB_TX) {                // transpose x -> Xth
        const int t = bid - RB_TB;
        transpose_body(g_Xth, x_g2, t & 31, t >> 5, tx, ty, tile);
    } else if (bid < RB_TR) {                // transpose root -> Bth[30]
        const int t = bid - RB_TX;
        transpose_body(g_Bth + ((size_t)PNB << 20), root, t & 31, t >> 5, tx, ty, tile);
    } else if (bid < RB_CX) {                // convert x -> Xh
        const size_t i = (size_t)(bid - RB_TR) * 256 + tid;
        if (i < ((size_t)PN2 * PN2) / 8) {
            float4 f0 = ((const float4*)x_g2)[2 * i];
            float4 f1 = ((const float4*)x_g2)[2 * i + 1];
            __half2 h[4];
            h[0] = __floats2half2_rn(f0.x, f0.y);
            h[1] = __floats2half2_rn(f0.z, f0.w);
            h[2] = __floats2half2_rn(f1.x, f1.y);
            h[3] = __floats2half2_rn(f1.z, f1.w);
            ((float4*)g_Xh)[i] = *(float4*)h;
        }
    } else {                                  // transpose W (128x128) -> Wth
        const int t = bid - RB_CX;
        const int bx = t & 3, by = t >> 2;
        int c = bx * 32 + tx, r = by * 32 + ty;
#pragma unroll
        for (int i = 0; i < 32; i += 8)
            tile[ty + i][tx] = W_stc[(r + i) * PD + c];
        __syncthreads();
        c = by * 32 + tx; r = bx * 32 + ty;
#pragma unroll
        for (int i = 0; i < 32; i += 8)
            g_Wth[(r + i) * PD + c] = __float2half_rn(tile[tx][ty + i]);
    }
}

// =====================================================================
// build_A (fp32 atomics) + convert to fp16
// =====================================================================
__global__ void build_A_kernel(const void* __restrict__ ei,
                               const void* __restrict__ et,
                               const float* __restrict__ att) {
    int e = blockIdx.x * blockDim.x + threadIdx.x;
    if (e >= PE2) return;
    const int s = load_idx(ei, e);
    const int d = load_idx(ei, (size_t)PE2 + e);
    const int t = load_idx(et, e);
    const float w = 1.0f / fmaxf(g_deg2[d], 1.0f);
    const float* ar = att + (size_t)t * PNB;
    float* base = g_A + (size_t)d * PN2 + s;
#pragma unroll
    for (int b = 0; b < PNB; b++)
        atomicAdd(base + ((size_t)b << 20), ar[b] * w);
}

__global__ void convert_A_kernel() {
    const size_t i = (size_t)blockIdx.x * blockDim.x + threadIdx.x;
    if (i >= ((size_t)PNB << 20) / 8) return;
    float4 f0 = ((const float4*)g_A)[2 * i];
    float4 f1 = ((const float4*)g_A)[2 * i + 1];
    __half2 h[4];
    h[0] = __floats2half2_rn(f0.x, f0.y);
    h[1] = __floats2half2_rn(f0.z, f0.w);
    h[2] = __floats2half2_rn(f1.x, f1.y);
    h[3] = __floats2half2_rn(f1.z, f1.w);
    ((float4*)g_Ah)[i] = *(float4*)h;
}

// =====================================================================
// fused_main: gemm1 (S[z] = A[z] @ X) tiles + scatter1 (grid-stride)
// =====================================================================
__global__ __launch_bounds__(256, 2) void fused_main(const float* __restrict__ xg1,
                                                     const void* __restrict__ ei1) {
    __shared__ __half As[4 * STAGE_B / 2];
    __shared__ __half Bs[4 * STAGE_B / 2];
    const int bid = blockIdx.x, tid = threadIdx.x;

    if (bid < NG1) {
        // ---- gemm1 role ----
        const int z = bid >> 6;
        const int m0 = ((bid >> 3) & 7) * 128;
        const int n0 = (bid & 7) * 128;
        const __half* A = g_Ah + ((size_t)z << 20);
        __half* C = g_Sh + ((size_t)z << 20);
        const int lane = tid & 31, warp = tid >> 5;
        const int wm = (warp >> 1) * 32, wn = (warp & 1) * 64;
        const int r = tid >> 1;
        const uint32_t sdst = r * ROW_B + (tid & 1) * 16;
        const uint32_t AsU = smem_u32(As), BsU = smem_u32(Bs);
        const __half* ap = A + (size_t)(m0 + r) * PN2 + (tid & 1) * 8;
        const __half* bp = g_Xth + (size_t)(n0 + r) * PN2 + (tid & 1) * 8;
        const int base_a = (wm + (lane & 15)) * ROW_B + (lane >> 4) * 16;
        const int base_b = (wn + (lane & 15)) * ROW_B + (lane >> 4) * 16;

        float acc[2][8][4];
#pragma unroll
        for (int i = 0; i < 2; i++)
#pragma unroll
            for (int j = 0; j < 8; j++)
#pragma unroll
                for (int k = 0; k < 4; k++) acc[i][j][k] = 0.0f;

        const int NT = 64;
#pragma unroll
        for (int s = 0; s < 3; s++) {
            cp16(AsU + s * STAGE_B + sdst, ap + s * 16);
            cp16(BsU + s * STAGE_B + sdst, bp + s * 16);
            CP_COMMIT();
        }
#pragma unroll 1
        for (int t = 0; t < NT; t++) {
            CP_WAIT2();
            __syncthreads();
            if (t + 3 < NT) {
                const uint32_t nx = ((t + 3) & 3) * STAGE_B;
                cp16(AsU + nx + sdst, ap + (t + 3) * 16);
                cp16(BsU + nx + sdst, bp + (t + 3) * 16);
                CP_COMMIT();
            }
            const uint32_t cur = (t & 3) * STAGE_B;
            compute_k16(AsU + cur, BsU + cur, base_a, base_b, acc);
        }
#pragma unroll
        for (int mt = 0; mt < 2; mt++)
#pragma unroll
            for (int nt = 0; nt < 8; nt++) {
                const int rr = m0 + wm + mt * 16 + (lane >> 2);
                const int cc = n0 + wn + nt * 8 + (lane & 3) * 2;
                *(__half2*)&C[(size_t)rr * PN2 + cc] =
                    __floats2half2_rn(acc[mt][nt][0], acc[mt][nt][1]);
                *(__half2*)&C[(size_t)(rr + 8) * PN2 + cc] =
                    __floats2half2_rn(acc[mt][nt][2], acc[mt][nt][3]);
            }
    } else {
        // ---- scatter1 role: one warp per edge, grid-stride ----
        const unsigned gw = (unsigned)(bid - NG1) * 8u + (tid >> 5);
        const int lane = tid & 31;
        for (size_t e = gw; e < PE1; e += SC_STRIDE) {
            const int s = load_idx(ei1, e);
            const int d = load_idx(ei1, (size_t)PE1 + e);
            float4 v = *(const float4*)(xg1 + (size_t)s * PD + lane * 4);
            float* a = g_agg1 + (size_t)d * PD + lane * 4;
            asm volatile("red.global.add.v4.f32 [%0], {%1,%2,%3,%4};"
                         :: "l"(a), "f"(v.x), "f"(v.y), "f"(v.z), "f"(v.w)
                         : "memory");
            if (lane == 0) atomicAdd(&g_deg1[d], 1.0f);
        }
    }
}

// =====================================================================
// fused_tail: gemm_acc split-K tiles + linear1 MMA blocks (smem union)
// =====================================================================
__global__ __launch_bounds__(256, 2) void fused_tail(const float* __restrict__ bias1,
                                                     float* __restrict__ out1) {
    __shared__ __align__(16) char sraw[49152];
    const int bid = blockIdx.x, tid = threadIdx.x;
    const int lane = tid & 31, warp = tid >> 5;
    const int wm = (warp >> 1) * 32, wn = (warp & 1) * 64;

    if (bid < 512) {
        // ---- gemm_acc role ----
        __half* As = (__half*)sraw;
        __half* Bs = (__half*)(sraw + 24576);
        const int m0 = ((bid >> 3) & 7) * 128;
        const int n0 = (bid & 7) * 128;
        const int kt0 = (bid >> 6) * KT_ACC;
        const int r = tid >> 1;
        const uint32_t sdst = r * ROW_B + (tid & 1) * 16;
        const uint32_t AsU = smem_u32(As), BsU = smem_u32(Bs);
        const int base_a = (wm + (lane & 15)) * ROW_B + (lane >> 4) * 16;
        const int base_b = (wn + (lane & 15)) * ROW_B + (lane >> 4) * 16;

        auto srcA = [&](int kt) -> const __half* {
            if (kt < PNB * 64)
                return g_Sh + ((size_t)(kt >> 6) << 20) + (size_t)(m0 + r) * PN2 +
                       ((kt & 63) << 4) + (tid & 1) * 8;
            return g_Xh + (size_t)(m0 + r) * PN2 + ((kt - PNB * 64) << 4) + (tid & 1) * 8;
        };
        auto srcB = [&](int kt) -> const __half* {
            return g_Bth + ((size_t)(kt >> 6) << 20) + (size_t)(n0 + r) * PN2 +
                   ((kt & 63) << 4) + (tid & 1) * 8;
        };

        float acc[2][8][4];
#pragma unroll
        for (int i = 0; i < 2; i++)
#pragma unroll
            for (int j = 0; j < 8; j++)
#pragma unroll
                for (int k = 0; k < 4; k++) acc[i][j][k] = 0.0f;

#pragma unroll
        for (int s = 0; s < 3; s++) {
            cp16(AsU + s * STAGE_B + sdst, srcA(kt0 + s));
            cp16(BsU + s * STAGE_B + sdst, srcB(kt0 + s));
            CP_COMMIT();
        }
#pragma unroll 1
        for (int t = 0; t < KT_ACC; t++) {
            CP_WAIT2();
            __syncthreads();
            if (t + 3 < KT_ACC) {
                const uint32_t nx = ((t + 3) & 3) * STAGE_B;
                cp16(AsU + nx + sdst, srcA(kt0 + t + 3));
                cp16(BsU + nx + sdst, srcB(kt0 + t + 3));
                CP_COMMIT();
            }
            const uint32_t cur = (t & 3) * STAGE_B;
            compute_k16(AsU + cur, BsU + cur, base_a, base_b, acc);
        }
#pragma unroll
        for (int mt = 0; mt < 2; mt++)
#pragma unroll
            for (int nt = 0; nt < 8; nt++) {
                const int rr = m0 + wm + mt * 16 + (lane >> 2);
                const int cc = n0 + wn + nt * 8 + (lane & 3) * 2;
                atomicAdd(&g_h2[(size_t)rr * PN2 + cc],           acc[mt][nt][0]);
                atomicAdd(&g_h2[(size_t)rr * PN2 + cc + 1],       acc[mt][nt][1]);
                atomicAdd(&g_h2[(size_t)(rr + 8) * PN2 + cc],     acc[mt][nt][2]);
                atomicAdd(&g_h2[(size_t)(rr + 8) * PN2 + cc + 1], acc[mt][nt][3]);
            }
    } else {
        // ---- linear1 role ----
        __half* Asl = (__half*)sraw;                        // 128*72 halves
        __half* Bsl = (__half*)(sraw + 18432);
        float* bsm    = (float*)(sraw + 36864);             // 128 floats
        float* rowmax = (float*)(sraw + 37376);             // [2][128]
        float* rowsum = (float*)(sraw + 38400);             // [2][128]
        const int row0 = (bid - 512) * 128;
        const uint32_t AsU = smem_u32(Asl), BsU = smem_u32(Bsl);
        if (tid < PD) bsm[tid] = bias1[tid];

        float acc[2][8][4];
#pragma unroll
        for (int i = 0; i < 2; i++)
#pragma unroll
            for (int j = 0; j < 8; j++)
#pragma unroll
                for (int k = 0; k < 4; k++) acc[i][j][k] = 0.0f;

        const int base_a = (wm + (lane & 15)) * 144 + (lane >> 4) * 16;
        const int base_b = (wn + (lane & 15)) * 144 + (lane >> 4) * 16;

#pragma unroll 1
        for (int kc = 0; kc < 2; kc++) {
            __syncthreads();
#pragma unroll
            for (int it = 0; it < 4; it++) {
                const int task = tid + it * 256;
                const int r = task >> 3, cg = (task & 7) * 8;
                const int grow = row0 + r;
                __half2 h[4];
                if (grow < PN1) {
                    const float invd = 1.0f / fmaxf(g_deg1[grow], 1.0f);
                    const float* p = g_agg1 + (size_t)grow * PD + kc * 64 + cg;
                    float4 f0 = *(const float4*)p, f1 = *(const float4*)(p + 4);
                    h[0] = __floats2half2_rn(f0.x * invd, f0.y * invd);
                    h[1] = __floats2half2_rn(f0.z * invd, f0.w * invd);
                    h[2] = __floats2half2_rn(f1.x * invd, f1.y * invd);
                    h[3] = __floats2half2_rn(f1.z * invd, f1.w * invd);
                } else {
                    h[0] = h[1] = h[2] = h[3] = __floats2half2_rn(0.f, 0.f);
                }
                *(float4*)&Asl[r * LROW_H + cg] = *(float4*)h;
            }
#pragma unroll
            for (int it = 0; it < 4; it++) {
                const int task = tid + it * 256;
                const int n = task >> 3, kg = (task & 7) * 8;
                *(float4*)&Bsl[n * LROW_H + kg] =
                    *(const float4*)&g_Wth[n * PD + kc * 64 + kg];
            }
            __syncthreads();
#pragma unroll
            for (int ks = 0; ks < 4; ks++) {
                uint32_t a0[4], a1[4];
                ldsm4(a0[0], a0[1], a0[2], a0[3], AsU + base_a + ks * 32);
                ldsm4(a1[0], a1[1], a1[2], a1[3], AsU + base_a + 16 * 144 + ks * 32);
#pragma unroll
                for (int j = 0; j < 4; j++) {
                    uint32_t b0, b1, b2, b3;
                    ldsm4(b0, b1, b2, b3, BsU + base_b + j * (16 * 144) + ks * 32);
                    mma_f16(acc[0][2 * j],     a0[0], a0[1], a0[2], a0[3], b0, b2);
                    mma_f16(acc[0][2 * j + 1], a0[0], a0[1], a0[2], a0[3], b1, b3);
                    mma_f16(acc[1][2 * j],     a1[0], a1[1], a1[2], a1[3], b0, b2);
                    mma_f16(acc[1][2 * j + 1], a1[0], a1[1], a1[2], a1[3], b1, b3);
                }
            }
        }

        // epilogue: bias + relu + log_softmax
#pragma unroll
        for (int mt = 0; mt < 2; mt++)
#pragma unroll
            for (int nt = 0; nt < 8; nt++) {
                const int cc = wn + nt * 8 + (lane & 3) * 2;
                const float b0 = bsm[cc], b1 = bsm[cc + 1];
                acc[mt][nt][0] = fmaxf(acc[mt][nt][0] + b0, 0.f);
                acc[mt][nt][1] = fmaxf(acc[mt][nt][1] + b1, 0.f);
                acc[mt][nt][2] = fmaxf(acc[mt][nt][2] + b0, 0.f);
                acc[mt][nt][3] = fmaxf(acc[mt][nt][3] + b1, 0.f);
            }
        float mr[2][2];
#pragma unroll
        for (int mt = 0; mt < 2; mt++) {
            mr[mt][0] = 0.f; mr[mt][1] = 0.f;
#pragma unroll
            for (int nt = 0; nt < 8; nt++) {
                mr[mt][0] = fmaxf(mr[mt][0], fmaxf(acc[mt][nt][0], acc[mt][nt][1]));
                mr[mt][1] = fmaxf(mr[mt][1], fmaxf(acc[mt][nt][2], acc[mt][nt][3]));
            }
#pragma unroll
            for (int o = 1; o <= 2; o <<= 1) {
                mr[mt][0] = fmaxf(mr[mt][0], __shfl_xor_sync(0xffffffffu, mr[mt][0], o));
                mr[mt][1] = fmaxf(mr[mt][1], __shfl_xor_sync(0xffffffffu, mr[mt][1], o));
            }
        }
        if ((lane & 3) == 0) {
#pragma unroll
            for (int mt = 0; mt < 2; mt++) {
                rowmax[(warp & 1) * 128 + wm + mt * 16 + (lane >> 2)]     = mr[mt][0];
                rowmax[(warp & 1) * 128 + wm + mt * 16 + (lane >> 2) + 8] = mr[mt][1];
            }
        }
        __syncthreads();
        float M[2][2], sr[2][2];
#pragma unroll
        for (int mt = 0; mt < 2; mt++) {
            const int rb = wm + mt * 16 + (lane >> 2);
            M[mt][0] = fmaxf(rowmax[rb], rowmax[128 + rb]);
            M[mt][1] = fmaxf(rowmax[rb + 8], rowmax[128 + rb + 8]);
            sr[mt][0] = 0.f; sr[mt][1] = 0.f;
#pragma unroll
            for (int nt = 0; nt < 8; nt++) {
                sr[mt][0] += __expf(acc[mt][nt][0] - M[mt][0]) +
                             __expf(acc[mt][nt][1] - M[mt][0]);
                sr[mt][1] += __expf(acc[mt][nt][2] - M[mt][1]) +
                             __expf(acc[mt][nt][3] - M[mt][1]);
            }
#pragma unroll
            for (int o = 1; o <= 2; o <<= 1) {
                sr[mt][0] += __shfl_xor_sync(0xffffffffu, sr[mt][0], o);
                sr[mt][1] += __shfl_xor_sync(0xffffffffu, sr[mt][1], o);
            }
        }
        if ((lane & 3) == 0) {
#pragma unroll
            for (int mt = 0; mt < 2; mt++) {
                rowsum[(warp & 1) * 128 + wm + mt * 16 + (lane >> 2)]     = sr[mt][0];
                rowsum[(warp & 1) * 128 + wm + mt * 16 + (lane >> 2) + 8] = sr[mt][1];
            }
        }
        __syncthreads();
#pragma unroll
        for (int mt = 0; mt < 2; mt++) {
            const int rb = wm + mt * 16 + (lane >> 2);
            const float lse0 = M[mt][0] + __logf(rowsum[rb] + rowsum[128 + rb]);
            const float lse1 = M[mt][1] + __logf(rowsum[rb + 8] + rowsum[128 + rb + 8]);
            const int r1 = row0 + rb;
#pragma unroll
            for (int nt = 0; nt < 8; nt++) {
                const int cc = wn + nt * 8 + (lane & 3) * 2;
                if (r1 < PN1)
                    *(float2*)&out1[(size_t)r1 * PD + cc] =
                        make_float2(acc[mt][nt][0] - lse0, acc[mt][nt][1] - lse0);
                if (r1 + 8 < PN1)
                    *(float2*)&out1[(size_t)(r1 + 8) * PD + cc] =
                        make_float2(acc[mt][nt][2] - lse1, acc[mt][nt][3] - lse1);
            }
        }
    }
}

// =====================================================================
// out2 epilogue
// =====================================================================
__global__ __launch_bounds__(256) void epilogue2_kernel(const float* __restrict__ bias,
                                                        float* __restrict__ out2) {
    const int row = blockIdx.x, tid = threadIdx.x;
    __shared__ float sred[8];
    __shared__ float sbcast;
    float4 v = *(const float4*)(g_h2 + (size_t)row * PN2 + tid * 4);
    float4 b = *(const float4*)(bias + tid * 4);
    v.x = fmaxf(v.x + b.x, 0.0f);
    v.y = fmaxf(v.y + b.y, 0.0f);
    v.z = fmaxf(v.z + b.z, 0.0f);
    v.w = fmaxf(v.w + b.w, 0.0f);
    float m = fmaxf(fmaxf(v.x, v.y), fmaxf(v.z, v.w));
#pragma unroll
    for (int o = 16; o; o >>= 1) m = fmaxf(m, __shfl_xor_sync(0xffffffffu, m, o));
    if ((tid & 31) == 0) sred[tid >> 5] = m;
    __syncthreads();
    if (tid == 0) {
        float t = sred[0];
#pragma unroll
        for (int i = 1; i < 8; i++) t = fmaxf(t, sred[i]);
        sbcast = t;
    }
    __syncthreads();
    m = sbcast;
    float s = __expf(v.x - m) + __expf(v.y - m) + __expf(v.z - m) + __expf(v.w - m);
#pragma unroll
    for (int o = 16; o; o >>= 1) s += __shfl_xor_sync(0xffffffffu, s, o);
    __syncthreads();
    if ((tid & 31) == 0) sred[tid >> 5] = s;
    __syncthreads();
    if (tid == 0) {
        float t = 0.0f;
#pragma unroll
        for (int i = 0; i < 8; i++) t += sred[i];
        sbcast = m + __logf(t);
    }
    __syncthreads();
    const float lse = sbcast;
    *(float4*)(out2 + (size_t)row * PN2 + tid * 4) =
        make_float4(v.x - lse, v.y - lse, v.z - lse, v.w - lse);
}

// =====================================================================
// launch — kernel launches ONLY (7 launches)
// =====================================================================
extern "C" void kernel_launch(void* const* d_in, const int* in_sizes, int n_in,
                              void* d_out, int out_size) {
    (void)in_sizes; (void)n_in; (void)out_size;
    const float* x_g1      = (const float*)d_in[0];
    const float* W_stc     = (const float*)d_in[1];
    const float* b_stc     = (const float*)d_in[2];
    const float* x_g2      = (const float*)d_in[3];
    const float* basis     = (const float*)d_in[4];
    const float* att       = (const float*)d_in[5];
    const float* root      = (const float*)d_in[6];
    const float* bias_rgcn = (const float*)d_in[7];
    const void*  ei1       = d_in[8];
    const void*  ei2       = d_in[9];
    const void*  et2       = d_in[10];
    float* out1 = (float*)d_out;
    float* out2 = out1 + (size_t)PN1 * PD;

    probe_kernel<<<1, 256>>>((const int*)ei1);                         // 0
    fused_prep<<<PREP_GRID, 256>>>(x_g2, basis, root, W_stc, ei2);     // 1
    build_A_kernel<<<(PE2 + 255) / 256, 256>>>(ei2, et2, att);         // 2
    convert_A_kernel<<<15360, 256>>>();                                // 3
    fused_main<<<NG1 + NSC, 256>>>(x_g1, ei1);                         // 4
    fused_tail<<<512 + 782, 256>>>(b_stc, out1);                       // 5
    epilogue2_kernel<<<PN2, 256>>>(bias_rgcn, out2);                   // 6
}